// round 13
// baseline (speedup 1.0000x reference)
#include <cuda_runtime.h>
#include <cuda_fp16.h>
#include <stdint.h>

#define BATCH 4
#define SEQ   2048
#define NH    16
#define DHEAD 64
#define DMODEL 1024

// Scratch (allocation-free rule: __device__ globals)
__device__ __half g_xh [(size_t)BATCH*SEQ*DMODEL];          // fp16 x
__device__ __half g_wqh[(size_t)NH*DHEAD*DMODEL];           // [h][d][m]
__device__ __half g_wkh[(size_t)NH*DHEAD*DMODEL];
__device__ __half g_wvh[(size_t)NH*DHEAD*DMODEL];
__device__ __half g_woh[(size_t)DMODEL*DMODEL];             // [n][k]
__device__ __half g_q  [(size_t)BATCH*NH*SEQ*DHEAD];        // [bh][s][d] (pre-scaled)
__device__ __half g_k  [(size_t)BATCH*NH*SEQ*DHEAD];
__device__ __half g_v  [(size_t)BATCH*NH*SEQ*DHEAD];
__device__ __half g_vt [(size_t)BATCH*NH*DHEAD*SEQ];        // [bh][d][s]
__device__ __half g_att[(size_t)BATCH*SEQ*DMODEL];          // fp16 attention out

__device__ __forceinline__ uint32_t s2u(const void* p){
    return (uint32_t)__cvta_generic_to_shared(p);
}
__device__ __forceinline__ void ldsm4(unsigned r[4], uint32_t addr){
    asm volatile("ldmatrix.sync.aligned.m8n8.x4.shared.b16 {%0,%1,%2,%3}, [%4];"
        : "=r"(r[0]), "=r"(r[1]), "=r"(r[2]), "=r"(r[3]) : "r"(addr));
}
__device__ __forceinline__ void mma_f16(float* d, const unsigned* a, const unsigned* b){
    asm volatile(
        "mma.sync.aligned.m16n8k16.row.col.f32.f16.f16.f32 "
        "{%0,%1,%2,%3},{%4,%5,%6,%7},{%8,%9},{%0,%1,%2,%3};\n"
        : "+f"(d[0]), "+f"(d[1]), "+f"(d[2]), "+f"(d[3])
        : "r"(a[0]), "r"(a[1]), "r"(a[2]), "r"(a[3]), "r"(b[0]), "r"(b[1]));
}
__device__ __forceinline__ void cpa16(uint32_t dst, const void* src){
    asm volatile("cp.async.cg.shared.global [%0], [%1], 16;\n" :: "r"(dst), "l"(src));
}
__device__ __forceinline__ void cpa_commit(){
    asm volatile("cp.async.commit_group;\n" ::: "memory");
}
template<int N>
__device__ __forceinline__ void cpa_wait(){
    asm volatile("cp.async.wait_group %0;\n" :: "n"(N) : "memory");
}
__device__ __forceinline__ unsigned h2u(__half2 h){ return *(unsigned*)&h; }
__device__ __forceinline__ float ex2f(float x){
    float r; asm("ex2.approx.f32 %0, %1;" : "=f"(r) : "f"(x)); return r;
}
#define L2E 1.4426950408889634f

// ldmatrix x4 fragment address: rows of 8 16B chunks, SW128 XOR swizzle.
__device__ __forceinline__ uint32_t frag_addr(uint32_t base, int row0, int kc, int lane){
    const int row = row0 + (lane & 7) + ((lane >> 3) & 1) * 8;
    const int cc  = kc + (lane >> 4);
    return base + (uint32_t)row*128u + (uint32_t)((cc ^ (lane & 7)) * 16);
}

// ---------------------------------------------------------------------------
// Prework
// ---------------------------------------------------------------------------
__global__ void cvt_x_kernel(const float* __restrict__ x)
{
    const size_t n4 = (size_t)BATCH*SEQ*DMODEL/4;
    for (size_t i = blockIdx.x*blockDim.x + threadIdx.x; i < n4;
         i += (size_t)gridDim.x*blockDim.x) {
        float4 v = ((const float4*)x)[i];
        __half2 lo = __floats2half2_rn(v.x, v.y);
        __half2 hi = __floats2half2_rn(v.z, v.w);
        ((uint2*)g_xh)[i] = make_uint2(h2u(lo), h2u(hi));
    }
}

// fused Q/K/V weight transpose: z in [0,48), 16 heads per proj
__global__ void trw_qkv_kernel(const float* __restrict__ Qw,
                               const float* __restrict__ Kw,
                               const float* __restrict__ Vw)
{
    __shared__ float tile[32][33];
    const int z = blockIdx.z, h = z & 15, proj = z >> 4;
    const float* in = (proj == 0) ? Qw : (proj == 1) ? Kw : Vw;
    __half* out = (proj == 0) ? g_wqh : (proj == 1) ? g_wkh : g_wvh;
    const size_t boff = (size_t)h * DMODEL * DHEAD;
    const int c0 = blockIdx.x*32, r0 = blockIdx.y*32;
    const int tx = threadIdx.x, ty = threadIdx.y;   // 32 x 8
    #pragma unroll
    for (int i = 0; i < 32; i += 8)
        tile[ty+i][tx] = in[boff + (size_t)(r0+ty+i)*DHEAD + c0+tx];
    __syncthreads();
    #pragma unroll
    for (int i = 0; i < 32; i += 8)
        out[boff + (size_t)(c0+ty+i)*DMODEL + r0+tx] = __float2half_rn(tile[tx][ty+i]);
}

__global__ void trw_kernel(const float* __restrict__ in, __half* __restrict__ out,
                           int rows, int cols)
{
    __shared__ float tile[32][33];
    const size_t iboff = (size_t)blockIdx.z * rows * cols;
    const int c0 = blockIdx.x*32, r0 = blockIdx.y*32;
    const int tx = threadIdx.x, ty = threadIdx.y;   // 32 x 8
    #pragma unroll
    for (int i = 0; i < 32; i += 8)
        tile[ty+i][tx] = in[iboff + (size_t)(r0+ty+i)*cols + c0+tx];
    __syncthreads();
    #pragma unroll
    for (int i = 0; i < 32; i += 8)
        out[iboff + (size_t)(c0+ty+i)*rows + r0+tx] = __float2half_rn(tile[tx][ty+i]);
}

__global__ void trv_kernel()
{
    __shared__ __half tile[32][33];
    const size_t bo = (size_t)blockIdx.z * SEQ * DHEAD;
    const size_t bt = (size_t)blockIdx.z * DHEAD * SEQ;
    const int s0 = blockIdx.x*32, d0 = blockIdx.y*32;
    const int tx = threadIdx.x, ty = threadIdx.y;   // 32 x 8
    #pragma unroll
    for (int i = 0; i < 32; i += 8)
        tile[ty+i][tx] = g_v[bo + (size_t)(s0+ty+i)*DHEAD + d0+tx];
    __syncthreads();
    #pragma unroll
    for (int i = 0; i < 32; i += 8)
        g_vt[bt + (size_t)(d0+ty+i)*SEQ + s0+tx] = tile[tx][ty+i];
}

// ---------------------------------------------------------------------------
// fp16 GEMM core: C[128 x 128] = A[128 x 1024] * B[128 x 1024]^T
// 256 threads, 8 warps (2m x 4n), warp tile 64x32, BK=64, 2-stage cp.async,
// ONE barrier per k-iter.
// ---------------------------------------------------------------------------
#define GSTG 32768   // bytes per stage: A 16KB + B 16KB
#define GEMM_SMEM (2*GSTG)

__device__ __forceinline__ void gemm_mainloop128(
    const __half* __restrict__ A, const __half* __restrict__ Bt,
    float acc[4][4][4])
{
    extern __shared__ unsigned char sm[];
    const uint32_t sb = s2u(sm);

    const int t = threadIdx.x, lane = t & 31, warp = t >> 5;
    const int wm = warp >> 2, wn = warp & 3;

    uint32_t a_dst[4]; const __half* a_src[4];
    uint32_t b_dst[4]; const __half* b_src[4];
    #pragma unroll
    for (int j = 0; j < 4; j++) {
        const int id = t*4 + j, r = id >> 3, c = id & 7;
        const uint32_t sw = (uint32_t)(r*128 + ((c ^ (r&7))*16));
        a_dst[j] = sb + sw;
        b_dst[j] = sb + 16384u + sw;
        a_src[j] = A  + (size_t)r*DMODEL + c*8;
        b_src[j] = Bt + (size_t)r*DMODEL + c*8;
    }

    // prologue: stage 0
    #pragma unroll
    for (int j = 0; j < 4; j++) { cpa16(a_dst[j], a_src[j]); cpa16(b_dst[j], b_src[j]); }
    cpa_commit();

    const int iters = DMODEL / 64;   // 16
    for (int it = 0; it < iters; it++) {
        cpa_wait<0>();
        __syncthreads();   // stage cur visible to all; prev stage reads done

        if (it + 1 < iters) {
            const uint32_t off = (uint32_t)((it+1) & 1) * GSTG;
            #pragma unroll
            for (int j = 0; j < 4; j++) {
                cpa16(a_dst[j] + off, a_src[j] + (it+1)*64);
                cpa16(b_dst[j] + off, b_src[j] + (it+1)*64);
            }
            cpa_commit();
        }

        const uint32_t as = sb + (uint32_t)(it & 1) * GSTG;
        const uint32_t bs = as + 16384u;
        #pragma unroll
        for (int s = 0; s < 4; s++) {
            const int kc = s*2;
            unsigned af[4][4], bf0[4], bf1[4];
            #pragma unroll
            for (int mt = 0; mt < 4; mt++)
                ldsm4(af[mt], frag_addr(as, wm*64 + mt*16, kc, lane));
            ldsm4(bf0, frag_addr(bs, wn*32,      kc, lane));
            ldsm4(bf1, frag_addr(bs, wn*32 + 16, kc, lane));
            #pragma unroll
            for (int mt = 0; mt < 4; mt++)
                #pragma unroll
                for (int nt = 0; nt < 4; nt++) {
                    const unsigned* bsrc = (nt < 2) ? bf0 : bf1;
                    unsigned bb[2] = { bsrc[nt & 1], bsrc[(nt & 1) + 2] };
                    mma_f16(acc[mt][nt], af[mt], bb);
                }
        }
    }
}

// ---------------------------------------------------------------------------
// QKV projection (fp16 out; Q pre-scaled by 1/8). Grid (64 m, 24 n-tiles).
// ---------------------------------------------------------------------------
__global__ __launch_bounds__(256, 2) void qkv_kernel(
    const float* __restrict__ Qb, const float* __restrict__ Kb,
    const float* __restrict__ Vb)
{
    const int proj = blockIdx.y >> 3;        // 0..2
    const int nb   = (blockIdx.y & 7) * 128; // col base within proj
    const int rbase = blockIdx.x * 128;
    const int b     = rbase >> 11;
    const int srow  = rbase & 2047;

    const __half* W; const float* bias; __half* out;
    if (proj == 0)      { W = g_wqh; bias = Qb; out = g_q; }
    else if (proj == 1) { W = g_wkh; bias = Kb; out = g_k; }
    else                { W = g_wvh; bias = Vb; out = g_v; }

    float acc[4][4][4];
    #pragma unroll
    for (int i = 0; i < 4; i++)
        #pragma unroll
        for (int j = 0; j < 4; j++)
            #pragma unroll
            for (int c = 0; c < 4; c++) acc[i][j][c] = 0.f;

    gemm_mainloop128(g_xh + (size_t)rbase*DMODEL, W + (size_t)nb*DMODEL, acc);

    const int t = threadIdx.x, lane = t & 31, warp = t >> 5;
    const int wm = warp >> 2, wn = warp & 3;
    const int g = lane >> 2, tig = lane & 3;
    const float sc = (proj == 0) ? 0.125f : 1.0f;

    #pragma unroll
    for (int mt = 0; mt < 4; mt++) {
        #pragma unroll
        for (int nt = 0; nt < 4; nt++) {
            const int row = wm*64 + mt*16 + g;
            const int col = nb + wn*32 + nt*8 + 2*tig;   // within proj, 0..1023
            const int head = col >> 6, d = col & 63;
            const float b0 = bias[col], b1 = bias[col+1];
            __half* outp = out + (((size_t)(b*NH + head))*SEQ + srow + row)*DHEAD + d;
            *(__half2*)outp =
                __floats2half2_rn((acc[mt][nt][0] + b0)*sc, (acc[mt][nt][1] + b1)*sc);
            *(__half2*)(outp + 8*DHEAD) =
                __floats2half2_rn((acc[mt][nt][2] + b0)*sc, (acc[mt][nt][3] + b1)*sc);
        }
    }
}

// ---------------------------------------------------------------------------
// Output projection (fp32 out + bias). Grid (64 m, 8 n-tiles).
// ---------------------------------------------------------------------------
__global__ __launch_bounds__(256, 2) void oproj_kernel(
    const float* __restrict__ Ob, float* __restrict__ out)
{
    const int rbase = blockIdx.x * 128;
    const int nbase = blockIdx.y * 128;

    float acc[4][4][4];
    #pragma unroll
    for (int i = 0; i < 4; i++)
        #pragma unroll
        for (int j = 0; j < 4; j++)
            #pragma unroll
            for (int c = 0; c < 4; c++) acc[i][j][c] = 0.f;

    gemm_mainloop128(g_att + (size_t)rbase*DMODEL, g_woh + (size_t)nbase*DMODEL, acc);

    const int t = threadIdx.x, lane = t & 31, warp = t >> 5;
    const int wm = warp >> 2, wn = warp & 3;
    const int g = lane >> 2, tig = lane & 3;

    #pragma unroll
    for (int mt = 0; mt < 4; mt++) {
        #pragma unroll
        for (int nt = 0; nt < 4; nt++) {
            const int row = rbase + wm*64 + mt*16 + g;
            const int col = nbase + wn*32 + nt*8 + 2*tig;
            const float b0 = Ob[col], b1 = Ob[col+1];
            *(float2*)(out + (size_t)row*DMODEL + col) =
                make_float2(acc[mt][nt][0] + b0, acc[mt][nt][1] + b1);
            *(float2*)(out + (size_t)(row+8)*DMODEL + col) =
                make_float2(acc[mt][nt][2] + b0, acc[mt][nt][3] + b1);
        }
    }
}

// ---------------------------------------------------------------------------
// Causal flash attention, FA2-style. Block = (128 q rows, one (b,h)).
// 8 warps, each owns 16 full rows; softmax in registers; P in registers;
// Q fragments hoisted out of the kv loop; exp via FFMA+EX2.
// ---------------------------------------------------------------------------
#define AQ_OFF 0u          // Q: 128 rows x 128B = 16KB
#define AK_OFF 16384u      // K: 2 stages x 8KB
#define AV_OFF 32768u      // V: 2 stages x 8KB
#define ATTN_SMEM 49152

__global__ __launch_bounds__(256, 2) void attn_kernel()
{
    extern __shared__ unsigned char sm[];
    const uint32_t sb = s2u(sm);

    const int qt = (int)(gridDim.x - 1 - blockIdx.x);  // big tiles first
    const int bh = blockIdx.y;
    const int b  = bh >> 4;
    const int h  = bh & 15;

    const __half* Qp = g_q  + (size_t)bh*SEQ*DHEAD + (size_t)qt*128*DHEAD;
    const __half* Kp = g_k  + (size_t)bh*SEQ*DHEAD;
    const __half* Vt = g_vt + (size_t)bh*DHEAD*SEQ;

    const int t = threadIdx.x, lane = t & 31, warp = t >> 5;
    const int g = lane >> 2, tig = lane & 3;
    const int r_lo = warp*16 + g, r_hi = r_lo + 8;   // block-local q rows

    // staging maps
    uint32_t q_dst[4]; const __half* q_src[4];
    #pragma unroll
    for (int j = 0; j < 4; j++) {
        const int id = t*4 + j, r = id >> 3, c = id & 7;
        q_dst[j] = sb + AQ_OFF + (uint32_t)(r*128 + ((c ^ (r&7))*16));
        q_src[j] = Qp + (size_t)r*DHEAD + c*8;
    }
    uint32_t kv_dst[2]; int kv_r[2], kv_c[2];
    #pragma unroll
    for (int j = 0; j < 2; j++) {
        const int id = t*2 + j;
        kv_r[j] = id >> 3; kv_c[j] = id & 7;
        kv_dst[j] = (uint32_t)(kv_r[j]*128 + ((kv_c[j] ^ (kv_r[j]&7))*16));
    }

    // prologue: Q + K0 + V0
    #pragma unroll
    for (int j = 0; j < 4; j++) cpa16(q_dst[j], q_src[j]);
    #pragma unroll
    for (int j = 0; j < 2; j++) {
        cpa16(sb + AK_OFF + kv_dst[j], Kp + (size_t)kv_r[j]*DHEAD + kv_c[j]*8);
        cpa16(sb + AV_OFF + kv_dst[j], Vt + (size_t)kv_r[j]*SEQ + kv_c[j]*8);
    }
    cpa_commit();
    cpa_wait<0>();
    __syncthreads();

    // hoist Q fragments (loop-invariant)
    unsigned qf[4][4];
    #pragma unroll
    for (int s = 0; s < 4; s++)
        ldsm4(qf[s], frag_addr(sb + AQ_OFF, warp*16, s*2, lane));

    float m0 = -1e30f, m1 = -1e30f, l0 = 0.f, l1 = 0.f;
    float oacc[8][4];
    #pragma unroll
    for (int i = 0; i < 8; i++)
        #pragma unroll
        for (int j = 0; j < 4; j++) oacc[i][j] = 0.f;

    const int nkv = 2*qt + 2;   // 64-key tiles
    for (int kt = 0; kt < nkv; kt++) {
        const int cur = kt & 1, nxt = cur ^ 1;
        const bool more = (kt + 1 < nkv);

        if (more) {
            const __half* Kn = Kp + (size_t)(kt+1)*64*DHEAD;
            #pragma unroll
            for (int j = 0; j < 2; j++) {
                cpa16(sb + AK_OFF + (uint32_t)nxt*8192u + kv_dst[j],
                      Kn + (size_t)kv_r[j]*DHEAD + kv_c[j]*8);
                cpa16(sb + AV_OFF + (uint32_t)nxt*8192u + kv_dst[j],
                      Vt + (size_t)kv_r[j]*SEQ + (kt+1)*64 + kv_c[j]*8);
            }
            cpa_commit();
        }

        const uint32_t ks = sb + AK_OFF + (uint32_t)cur*8192u;
        const uint32_t vs = sb + AV_OFF + (uint32_t)cur*8192u;

        // S = Q * K^T  (m=16/warp, n=64 keys, k=64 d)
        float sacc[8][4];
        #pragma unroll
        for (int i = 0; i < 8; i++)
            #pragma unroll
            for (int j = 0; j < 4; j++) sacc[i][j] = 0.f;

        #pragma unroll
        for (int s = 0; s < 4; s++) {
            const int kc = s*2;
            unsigned bk[4][4];
            #pragma unroll
            for (int nb = 0; nb < 4; nb++)
                ldsm4(bk[nb], frag_addr(ks, nb*16, kc, lane));
            #pragma unroll
            for (int nt = 0; nt < 8; nt++) {
                const unsigned* bsrc = bk[nt >> 1];
                unsigned bb[2] = { bsrc[nt & 1], bsrc[(nt & 1) + 2] };
                mma_f16(sacc[nt], qf[s], bb);
            }
        }

        // causal mask: only top two kv tiles ((kt>>1)==qt). reference uses -1e5.
        if ((kt >> 1) == qt) {
            const int koff = (kt & 1) * 64;
            #pragma unroll
            for (int nt = 0; nt < 8; nt++) {
                const int c = koff + nt*8 + 2*tig;
                if (c     > r_lo) sacc[nt][0] = -100000.0f;
                if (c + 1 > r_lo) sacc[nt][1] = -100000.0f;
                if (c     > r_hi) sacc[nt][2] = -100000.0f;
                if (c + 1 > r_hi) sacc[nt][3] = -100000.0f;
            }
        }

        // row stats fully in-warp
        float pm0 = -1e30f, pm1 = -1e30f;
        #pragma unroll
        for (int nt = 0; nt < 8; nt++) {
            pm0 = fmaxf(pm0, fmaxf(sacc[nt][0], sacc[nt][1]));
            pm1 = fmaxf(pm1, fmaxf(sacc[nt][2], sacc[nt][3]));
        }
        pm0 = fmaxf(pm0, __shfl_xor_sync(0xffffffffu, pm0, 1));
        pm0 = fmaxf(pm0, __shfl_xor_sync(0xffffffffu, pm0, 2));
        pm1 = fmaxf(pm1, __shfl_xor_sync(0xffffffffu, pm1, 1));
        pm1 = fmaxf(pm1, __shfl_xor_sync(0xffffffffu, pm1, 2));

        const float mn0 = fmaxf(m0, pm0), mn1 = fmaxf(m1, pm1);
        const float c0 = mn0 * L2E, c1 = mn1 * L2E;
        const float f0 = ex2f(fmaf(m0, L2E, -c0));
        const float f1 = ex2f(fmaf(m1, L2E, -c1));
        m0 = mn0; m1 = mn1;

        // p = exp(s - m) via FFMA+EX2; P stays in registers as PV A-fragments
        unsigned ph[8][2];
        float ps0 = 0.f, ps1 = 0.f;
        #pragma unroll
        for (int nt = 0; nt < 8; nt++) {
            const float p0 = ex2f(fmaf(sacc[nt][0], L2E, -c0));
            const float p1 = ex2f(fmaf(sacc[nt][1], L2E, -c0));
            const float p2 = ex2f(fmaf(sacc[nt][2], L2E, -c1));
            const float p3 = ex2f(fmaf(sacc[nt][3], L2E, -c1));
            ps0 += p0 + p1; ps1 += p2 + p3;
            ph[nt][0] = h2u(__floats2half2_rn(p0, p1));
            ph[nt][1] = h2u(__floats2half2_rn(p2, p3));
            oacc[nt][0] *= f0; oacc[nt][1] *= f0;
            oacc[nt][2] *= f1; oacc[nt][3] *= f1;
        }
        ps0 += __shfl_xor_sync(0xffffffffu, ps0, 1);
        ps0 += __shfl_xor_sync(0xffffffffu, ps0, 2);
        ps1 += __shfl_xor_sync(0xffffffffu, ps1, 1);
        ps1 += __shfl_xor_sync(0xffffffffu, ps1, 2);
        l0 = l0*f0 + ps0;
        l1 = l1*f1 + ps1;

        // O += P * V : A from registers, B = Vt[d][key]
        #pragma unroll
        for (int s = 0; s < 4; s++) {
            unsigned a[4] = { ph[2*s][0], ph[2*s][1], ph[2*s+1][0], ph[2*s+1][1] };
            unsigned bv[4][4];
            #pragma unroll
            for (int nb = 0; nb < 4; nb++)
                ldsm4(bv[nb], frag_addr(vs, nb*16, s*2, lane));
            #pragma unroll
            for (int nt = 0; nt < 8; nt++) {
                const unsigned* bsrc = bv[nt >> 1];
                unsigned bb[2] = { bsrc[nt & 1], bsrc[(nt & 1) + 2] };
                mma_f16(oacc[nt], a, bb);
            }
        }
        cpa_wait<0>();
        __syncthreads();   // publish nxt; WAR-protect cur for next iter's loads
    }

    // normalize + write g_att (fp16): d = nt*8 + 2tig
    const float inv0 = 1.0f / l0, inv1 = 1.0f / l1;
    __half* outp = g_att + ((size_t)b*SEQ + (size_t)qt*128)*DMODEL + h*DHEAD;
    #pragma unroll
    for (int nt = 0; nt < 8; nt++) {
        const int d = nt*8 + 2*tig;
        *(__half2*)(outp + (size_t)r_lo*DMODEL + d) =
            __floats2half2_rn(oacc[nt][0]*inv0, oacc[nt][1]*inv0);
        *(__half2*)(outp + (size_t)r_hi*DMODEL + d) =
            __floats2half2_rn(oacc[nt][2]*inv1, oacc[nt][3]*inv1);
    }
}

extern "C" void kernel_launch(void* const* d_in, const int* in_sizes, int n_in,
                              void* d_out, int out_size)
{
    const float* x  = (const float*)d_in[0];
    const float* Qw = (const float*)d_in[1];
    const float* Qb = (const float*)d_in[2];
    const float* Kw = (const float*)d_in[3];
    const float* Kb = (const float*)d_in[4];
    const float* Vw = (const float*)d_in[5];
    const float* Vb = (const float*)d_in[6];
    const float* Ow = (const float*)d_in[7];
    const float* Ob = (const float*)d_in[8];
    float* out = (float*)d_out;

    __half* d_wo; cudaGetSymbolAddress((void**)&d_wo, g_woh);

    // prework: fp16 conversions + weight transposes
    cvt_x_kernel<<<2048, 256>>>(x);
    trw_qkv_kernel<<<dim3(2, 32, 48), dim3(32, 8)>>>(Qw, Kw, Vw);
    trw_kernel<<<dim3(32, 32, 1), dim3(32, 8)>>>(Ow, d_wo, DMODEL, DMODEL);

    cudaFuncSetAttribute(qkv_kernel,
                         cudaFuncAttributeMaxDynamicSharedMemorySize, GEMM_SMEM);
    cudaFuncSetAttribute(oproj_kernel,
                         cudaFuncAttributeMaxDynamicSharedMemorySize, GEMM_SMEM);
    cudaFuncSetAttribute(attn_kernel,
                         cudaFuncAttributeMaxDynamicSharedMemorySize, ATTN_SMEM);

    // QKV projection: 64 m-tiles x 24 (proj x 8 col-tiles)
    qkv_kernel<<<dim3(64, 24), 256, GEMM_SMEM>>>(Qb, Kb, Vb);

    // V transpose for attention B-operand
    trv_kernel<<<dim3(64, 2, BATCH*NH), dim3(32, 8)>>>();

    // Flash attention: 16 q-tiles x 64 (b,h)
    attn_kernel<<<dim3(16, 64), 256, ATTN_SMEM>>>();

    // Output projection: 64 m-tiles x 8 n-tiles
    oproj_kernel<<<dim3(64, 8), 256, GEMM_SMEM>>>(Ob, out);
}

// round 16
// speedup vs baseline: 1.5017x; 1.5017x over previous
#include <cuda_runtime.h>
#include <cuda_fp16.h>
#include <stdint.h>

#define BATCH 4
#define SEQ   2048
#define NH    16
#define DHEAD 64
#define DMODEL 1024

// Scratch (allocation-free rule: __device__ globals)
__device__ __half g_xh [(size_t)BATCH*SEQ*DMODEL];          // fp16 x
__device__ __half g_wqh[(size_t)NH*DHEAD*DMODEL];           // [h][d][m]
__device__ __half g_wkh[(size_t)NH*DHEAD*DMODEL];
__device__ __half g_wvh[(size_t)NH*DHEAD*DMODEL];
__device__ __half g_woh[(size_t)DMODEL*DMODEL];             // [n][k]
__device__ __half g_q  [(size_t)BATCH*NH*SEQ*DHEAD];        // [bh][s][d] (pre-scaled)
__device__ __half g_k  [(size_t)BATCH*NH*SEQ*DHEAD];
__device__ __half g_v  [(size_t)BATCH*NH*SEQ*DHEAD];
__device__ __half g_vt [(size_t)BATCH*NH*DHEAD*SEQ];        // [bh][d][s]
__device__ __half g_att[(size_t)BATCH*SEQ*DMODEL];          // fp16 attention out

__device__ __forceinline__ uint32_t s2u(const void* p){
    return (uint32_t)__cvta_generic_to_shared(p);
}
__device__ __forceinline__ void ldsm4(unsigned r[4], uint32_t addr){
    asm volatile("ldmatrix.sync.aligned.m8n8.x4.shared.b16 {%0,%1,%2,%3}, [%4];"
        : "=r"(r[0]), "=r"(r[1]), "=r"(r[2]), "=r"(r[3]) : "r"(addr));
}
__device__ __forceinline__ void mma_f16(float* d, const unsigned* a, const unsigned* b){
    asm volatile(
        "mma.sync.aligned.m16n8k16.row.col.f32.f16.f16.f32 "
        "{%0,%1,%2,%3},{%4,%5,%6,%7},{%8,%9},{%0,%1,%2,%3};\n"
        : "+f"(d[0]), "+f"(d[1]), "+f"(d[2]), "+f"(d[3])
        : "r"(a[0]), "r"(a[1]), "r"(a[2]), "r"(a[3]), "r"(b[0]), "r"(b[1]));
}
__device__ __forceinline__ void cpa16(uint32_t dst, const void* src){
    asm volatile("cp.async.cg.shared.global [%0], [%1], 16;\n" :: "r"(dst), "l"(src));
}
__device__ __forceinline__ void cpa_commit(){
    asm volatile("cp.async.commit_group;\n" ::: "memory");
}
template<int N>
__device__ __forceinline__ void cpa_wait(){
    asm volatile("cp.async.wait_group %0;\n" :: "n"(N) : "memory");
}
__device__ __forceinline__ unsigned h2u(__half2 h){ return *(unsigned*)&h; }

// ldmatrix x4 fragment address: rows of 8 16B chunks, SW128 XOR swizzle.
// row0 multiple of 16; kc = k-chunk base (k0/8).
__device__ __forceinline__ uint32_t frag_addr(uint32_t base, int row0, int kc, int lane){
    const int row = row0 + (lane & 7) + ((lane >> 3) & 1) * 8;
    const int cc  = kc + (lane >> 4);
    return base + (uint32_t)row*128u + (uint32_t)((cc ^ (lane & 7)) * 16);
}

// ---------------------------------------------------------------------------
// Prework
// ---------------------------------------------------------------------------
__global__ void cvt_x_kernel(const float* __restrict__ x)
{
    const size_t n4 = (size_t)BATCH*SEQ*DMODEL/4;
    for (size_t i = blockIdx.x*blockDim.x + threadIdx.x; i < n4;
         i += (size_t)gridDim.x*blockDim.x) {
        float4 v = ((const float4*)x)[i];
        __half2 lo = __floats2half2_rn(v.x, v.y);
        __half2 hi = __floats2half2_rn(v.z, v.w);
        ((uint2*)g_xh)[i] = make_uint2(h2u(lo), h2u(hi));
    }
}

// fused Q/K/V weight transpose: z in [0,48), 16 heads per proj
__global__ void trw_qkv_kernel(const float* __restrict__ Qw,
                               const float* __restrict__ Kw,
                               const float* __restrict__ Vw)
{
    __shared__ float tile[32][33];
    const int z = blockIdx.z, h = z & 15, proj = z >> 4;
    const float* in = (proj == 0) ? Qw : (proj == 1) ? Kw : Vw;
    __half* out = (proj == 0) ? g_wqh : (proj == 1) ? g_wkh : g_wvh;
    const size_t boff = (size_t)h * DMODEL * DHEAD;
    const int c0 = blockIdx.x*32, r0 = blockIdx.y*32;
    const int tx = threadIdx.x, ty = threadIdx.y;   // 32 x 8
    #pragma unroll
    for (int i = 0; i < 32; i += 8)
        tile[ty+i][tx] = in[boff + (size_t)(r0+ty+i)*DHEAD + c0+tx];
    __syncthreads();
    #pragma unroll
    for (int i = 0; i < 32; i += 8)
        out[boff + (size_t)(c0+ty+i)*DMODEL + r0+tx] = __float2half_rn(tile[tx][ty+i]);
}

__global__ void trw_kernel(const float* __restrict__ in, __half* __restrict__ out,
                           int rows, int cols)
{
    __shared__ float tile[32][33];
    const size_t iboff = (size_t)blockIdx.z * rows * cols;
    const int c0 = blockIdx.x*32, r0 = blockIdx.y*32;
    const int tx = threadIdx.x, ty = threadIdx.y;   // 32 x 8
    #pragma unroll
    for (int i = 0; i < 32; i += 8)
        tile[ty+i][tx] = in[iboff + (size_t)(r0+ty+i)*cols + c0+tx];
    __syncthreads();
    #pragma unroll
    for (int i = 0; i < 32; i += 8)
        out[iboff + (size_t)(c0+ty+i)*rows + r0+tx] = __float2half_rn(tile[tx][ty+i]);
}

__global__ void trv_kernel()
{
    __shared__ __half tile[32][33];
    const size_t bo = (size_t)blockIdx.z * SEQ * DHEAD;
    const size_t bt = (size_t)blockIdx.z * DHEAD * SEQ;
    const int s0 = blockIdx.x*32, d0 = blockIdx.y*32;
    const int tx = threadIdx.x, ty = threadIdx.y;   // 32 x 8
    #pragma unroll
    for (int i = 0; i < 32; i += 8)
        tile[ty+i][tx] = g_v[bo + (size_t)(s0+ty+i)*DHEAD + d0+tx];
    __syncthreads();
    #pragma unroll
    for (int i = 0; i < 32; i += 8)
        g_vt[bt + (size_t)(d0+ty+i)*SEQ + s0+tx] = tile[tx][ty+i];
}

// ---------------------------------------------------------------------------
// fp16 GEMM core: C[128 x 128] = A[128 x 1024] * B[128 x 1024]^T
// 256 threads, 8 warps (2m x 4n), warp tile 64x32, BK=64, 3-stage cp.async
// (two loads always in flight), R11 barrier structure.
// ---------------------------------------------------------------------------
#define GSTG 32768   // bytes per stage: A 16KB + B 16KB
#define GEMM_SMEM (3*GSTG)   // 98304

__device__ __forceinline__ void gemm_mainloop128(
    const __half* __restrict__ A, const __half* __restrict__ Bt,
    float acc[4][4][4])
{
    extern __shared__ unsigned char sm[];
    const uint32_t sb = s2u(sm);

    const int t = threadIdx.x, lane = t & 31, warp = t >> 5;
    const int wm = warp >> 2, wn = warp & 3;

    uint32_t a_dst[4]; const __half* a_src[4];
    uint32_t b_dst[4]; const __half* b_src[4];
    #pragma unroll
    for (int j = 0; j < 4; j++) {
        const int id = t*4 + j, r = id >> 3, c = id & 7;
        const uint32_t sw = (uint32_t)(r*128 + ((c ^ (r&7))*16));
        a_dst[j] = sb + sw;
        b_dst[j] = sb + 16384u + sw;
        a_src[j] = A  + (size_t)r*DMODEL + c*8;
        b_src[j] = Bt + (size_t)r*DMODEL + c*8;
    }

    // prologue: stages 0 and 1
    #pragma unroll
    for (int s = 0; s < 2; s++) {
        const uint32_t off = (uint32_t)s * GSTG;
        #pragma unroll
        for (int j = 0; j < 4; j++) {
            cpa16(a_dst[j] + off, a_src[j] + s*64);
            cpa16(b_dst[j] + off, b_src[j] + s*64);
        }
        cpa_commit();
    }

    const int iters = DMODEL / 64;   // 16
    for (int it = 0; it < iters; it++) {
        if (it + 2 < iters) {
            const uint32_t off = (uint32_t)((it+2) % 3) * GSTG;
            #pragma unroll
            for (int j = 0; j < 4; j++) {
                cpa16(a_dst[j] + off, a_src[j] + (it+2)*64);
                cpa16(b_dst[j] + off, b_src[j] + (it+2)*64);
            }
            cpa_commit();
            cpa_wait<2>();
        } else {
            cpa_wait<0>();
        }
        __syncthreads();

        const uint32_t as = sb + (uint32_t)(it % 3) * GSTG;
        const uint32_t bs = as + 16384u;
        #pragma unroll
        for (int s = 0; s < 4; s++) {
            const int kc = s*2;
            unsigned af[4][4], bf0[4], bf1[4];
            #pragma unroll
            for (int mt = 0; mt < 4; mt++)
                ldsm4(af[mt], frag_addr(as, wm*64 + mt*16, kc, lane));
            ldsm4(bf0, frag_addr(bs, wn*32,      kc, lane));
            ldsm4(bf1, frag_addr(bs, wn*32 + 16, kc, lane));
            #pragma unroll
            for (int mt = 0; mt < 4; mt++)
                #pragma unroll
                for (int nt = 0; nt < 4; nt++) {
                    const unsigned* bsrc = (nt < 2) ? bf0 : bf1;
                    unsigned bb[2] = { bsrc[nt & 1], bsrc[(nt & 1) + 2] };
                    mma_f16(acc[mt][nt], af[mt], bb);
                }
        }
        __syncthreads();
    }
}

// ---------------------------------------------------------------------------
// QKV projection (fp16 out; Q pre-scaled by 1/8). Grid (64 m, 24 n-tiles).
// ---------------------------------------------------------------------------
__global__ __launch_bounds__(256, 2) void qkv_kernel(
    const float* __restrict__ Qb, const float* __restrict__ Kb,
    const float* __restrict__ Vb)
{
    const int proj = blockIdx.y >> 3;        // 0..2
    const int nb   = (blockIdx.y & 7) * 128; // col base within proj
    const int rbase = blockIdx.x * 128;
    const int b     = rbase >> 11;
    const int srow  = rbase & 2047;

    const __half* W; const float* bias; __half* out;
    if (proj == 0)      { W = g_wqh; bias = Qb; out = g_q; }
    else if (proj == 1) { W = g_wkh; bias = Kb; out = g_k; }
    else                { W = g_wvh; bias = Vb; out = g_v; }

    float acc[4][4][4];
    #pragma unroll
    for (int i = 0; i < 4; i++)
        #pragma unroll
        for (int j = 0; j < 4; j++)
            #pragma unroll
            for (int c = 0; c < 4; c++) acc[i][j][c] = 0.f;

    gemm_mainloop128(g_xh + (size_t)rbase*DMODEL, W + (size_t)nb*DMODEL, acc);

    const int t = threadIdx.x, lane = t & 31, warp = t >> 5;
    const int wm = warp >> 2, wn = warp & 3;
    const int g = lane >> 2, tig = lane & 3;
    const float sc = (proj == 0) ? 0.125f : 1.0f;

    #pragma unroll
    for (int mt = 0; mt < 4; mt++) {
        #pragma unroll
        for (int nt = 0; nt < 4; nt++) {
            const int row = wm*64 + mt*16 + g;
            const int col = nb + wn*32 + nt*8 + 2*tig;   // within proj, 0..1023
            const int head = col >> 6, d = col & 63;
            const float b0 = bias[col], b1 = bias[col+1];
            __half* outp = out + (((size_t)(b*NH + head))*SEQ + srow + row)*DHEAD + d;
            *(__half2*)outp =
                __floats2half2_rn((acc[mt][nt][0] + b0)*sc, (acc[mt][nt][1] + b1)*sc);
            *(__half2*)(outp + 8*DHEAD) =
                __floats2half2_rn((acc[mt][nt][2] + b0)*sc, (acc[mt][nt][3] + b1)*sc);
        }
    }
}

// ---------------------------------------------------------------------------
// Output projection (fp32 out + bias). Grid (64 m, 8 n-tiles).
// ---------------------------------------------------------------------------
__global__ __launch_bounds__(256, 2) void oproj_kernel(
    const float* __restrict__ Ob, float* __restrict__ out)
{
    const int rbase = blockIdx.x * 128;
    const int nbase = blockIdx.y * 128;

    float acc[4][4][4];
    #pragma unroll
    for (int i = 0; i < 4; i++)
        #pragma unroll
        for (int j = 0; j < 4; j++)
            #pragma unroll
            for (int c = 0; c < 4; c++) acc[i][j][c] = 0.f;

    gemm_mainloop128(g_att + (size_t)rbase*DMODEL, g_woh + (size_t)nbase*DMODEL, acc);

    const int t = threadIdx.x, lane = t & 31, warp = t >> 5;
    const int wm = warp >> 2, wn = warp & 3;
    const int g = lane >> 2, tig = lane & 3;

    #pragma unroll
    for (int mt = 0; mt < 4; mt++) {
        #pragma unroll
        for (int nt = 0; nt < 4; nt++) {
            const int row = rbase + wm*64 + mt*16 + g;
            const int col = nbase + wn*32 + nt*8 + 2*tig;
            const float b0 = Ob[col], b1 = Ob[col+1];
            *(float2*)(out + (size_t)row*DMODEL + col) =
                make_float2(acc[mt][nt][0] + b0, acc[mt][nt][1] + b1);
            *(float2*)(out + (size_t)(row+8)*DMODEL + col) =
                make_float2(acc[mt][nt][2] + b0, acc[mt][nt][3] + b1);
        }
    }
}

// ---------------------------------------------------------------------------
// Causal flash attention, FA2-style (exact R11 known-good structure).
// Block = (128 q rows, one (b,h)). 8 warps, each owns 16 full rows;
// softmax in registers; P in registers; 1 barrier/tile.
// ---------------------------------------------------------------------------
#define AQ_OFF 0u          // Q: 128 rows x 128B = 16KB
#define AK_OFF 16384u      // K: 2 stages x 8KB
#define AV_OFF 32768u      // V: 2 stages x 8KB
#define ATTN_SMEM 49152

__global__ __launch_bounds__(256, 2) void attn_kernel()
{
    extern __shared__ unsigned char sm[];
    const uint32_t sb = s2u(sm);

    const int qt = (int)(gridDim.x - 1 - blockIdx.x);  // big tiles first
    const int bh = blockIdx.y;
    const int b  = bh >> 4;
    const int h  = bh & 15;

    const __half* Qp = g_q  + (size_t)bh*SEQ*DHEAD + (size_t)qt*128*DHEAD;
    const __half* Kp = g_k  + (size_t)bh*SEQ*DHEAD;
    const __half* Vt = g_vt + (size_t)bh*DHEAD*SEQ;

    const int t = threadIdx.x, lane = t & 31, warp = t >> 5;
    const int g = lane >> 2, tig = lane & 3;
    const int r_lo = warp*16 + g, r_hi = r_lo + 8;   // block-local q rows

    // staging maps
    uint32_t q_dst[4]; const __half* q_src[4];
    #pragma unroll
    for (int j = 0; j < 4; j++) {
        const int id = t*4 + j, r = id >> 3, c = id & 7;
        q_dst[j] = sb + AQ_OFF + (uint32_t)(r*128 + ((c ^ (r&7))*16));
        q_src[j] = Qp + (size_t)r*DHEAD + c*8;
    }
    uint32_t kv_dst[2]; int kv_r[2], kv_c[2];
    #pragma unroll
    for (int j = 0; j < 2; j++) {
        const int id = t*2 + j;
        kv_r[j] = id >> 3; kv_c[j] = id & 7;
        kv_dst[j] = (uint32_t)(kv_r[j]*128 + ((kv_c[j] ^ (kv_r[j]&7))*16));
    }

    // prologue: Q + K0 + V0
    #pragma unroll
    for (int j = 0; j < 4; j++) cpa16(q_dst[j], q_src[j]);
    #pragma unroll
    for (int j = 0; j < 2; j++) {
        cpa16(sb + AK_OFF + kv_dst[j], Kp + (size_t)kv_r[j]*DHEAD + kv_c[j]*8);
        cpa16(sb + AV_OFF + kv_dst[j], Vt + (size_t)kv_r[j]*SEQ + kv_c[j]*8);
    }
    cpa_commit();
    cpa_wait<0>();

    float m0 = -1e30f, m1 = -1e30f, l0 = 0.f, l1 = 0.f;
    float oacc[8][4];
    #pragma unroll
    for (int i = 0; i < 8; i++)
        #pragma unroll
        for (int j = 0; j < 4; j++) oacc[i][j] = 0.f;

    const int nkv = 2*qt + 2;   // 64-key tiles
    for (int kt = 0; kt < nkv; kt++) {
        __syncthreads();   // publish stage(cur); prev iter's reads complete
        const int cur = kt & 1, nxt = cur ^ 1;
        const bool more = (kt + 1 < nkv);

        if (more) {
            const __half* Kn = Kp + (size_t)(kt+1)*64*DHEAD;
            #pragma unroll
            for (int j = 0; j < 2; j++) {
                cpa16(sb + AK_OFF + (uint32_t)nxt*8192u + kv_dst[j],
                      Kn + (size_t)kv_r[j]*DHEAD + kv_c[j]*8);
                cpa16(sb + AV_OFF + (uint32_t)nxt*8192u + kv_dst[j],
                      Vt + (size_t)kv_r[j]*SEQ + (kt+1)*64 + kv_c[j]*8);
            }
        }
        cpa_commit();

        const uint32_t ks = sb + AK_OFF + (uint32_t)cur*8192u;
        const uint32_t vs = sb + AV_OFF + (uint32_t)cur*8192u;

        // S = Q * K^T  (m=16/warp, n=64 keys, k=64 d)
        float sacc[8][4];
        #pragma unroll
        for (int i = 0; i < 8; i++)
            #pragma unroll
            for (int j = 0; j < 4; j++) sacc[i][j] = 0.f;

        #pragma unroll
        for (int s = 0; s < 4; s++) {
            const int kc = s*2;
            unsigned af[4], bk[4][4];
            ldsm4(af, frag_addr(sb + AQ_OFF, warp*16, kc, lane));
            #pragma unroll
            for (int nb = 0; nb < 4; nb++)
                ldsm4(bk[nb], frag_addr(ks, nb*16, kc, lane));
            #pragma unroll
            for (int nt = 0; nt < 8; nt++) {
                const unsigned* bsrc = bk[nt >> 1];
                unsigned bb[2] = { bsrc[nt & 1], bsrc[(nt & 1) + 2] };
                mma_f16(sacc[nt], af, bb);
            }
        }

        // causal mask: only top two kv tiles ((kt>>1)==qt). reference uses -1e5.
        if ((kt >> 1) == qt) {
            const int koff = (kt & 1) * 64;
            #pragma unroll
            for (int nt = 0; nt < 8; nt++) {
                const int c = koff + nt*8 + 2*tig;
                if (c     > r_lo) sacc[nt][0] = -100000.0f;
                if (c + 1 > r_lo) sacc[nt][1] = -100000.0f;
                if (c     > r_hi) sacc[nt][2] = -100000.0f;
                if (c + 1 > r_hi) sacc[nt][3] = -100000.0f;
            }
        }

        // row stats fully in-warp (rows live in thread quads)
        float pm0 = -1e30f, pm1 = -1e30f;
        #pragma unroll
        for (int nt = 0; nt < 8; nt++) {
            pm0 = fmaxf(pm0, fmaxf(sacc[nt][0], sacc[nt][1]));
            pm1 = fmaxf(pm1, fmaxf(sacc[nt][2], sacc[nt][3]));
        }
        pm0 = fmaxf(pm0, __shfl_xor_sync(0xffffffffu, pm0, 1));
        pm0 = fmaxf(pm0, __shfl_xor_sync(0xffffffffu, pm0, 2));
        pm1 = fmaxf(pm1, __shfl_xor_sync(0xffffffffu, pm1, 1));
        pm1 = fmaxf(pm1, __shfl_xor_sync(0xffffffffu, pm1, 2));

        const float mn0 = fmaxf(m0, pm0), mn1 = fmaxf(m1, pm1);
        const float f0 = __expf(m0 - mn0), f1 = __expf(m1 - mn1);
        m0 = mn0; m1 = mn1;

        // p = exp(s - m); P stays in registers as PV A-fragments
        unsigned ph[8][2];
        float ps0 = 0.f, ps1 = 0.f;
        #pragma unroll
        for (int nt = 0; nt < 8; nt++) {
            const float p0 = __expf(sacc[nt][0] - mn0);
            const float p1 = __expf(sacc[nt][1] - mn0);
            const float p2 = __expf(sacc[nt][2] - mn1);
            const float p3 = __expf(sacc[nt][3] - mn1);
            ps0 += p0 + p1; ps1 += p2 + p3;
            ph[nt][0] = h2u(__floats2half2_rn(p0, p1));
            ph[nt][1] = h2u(__floats2half2_rn(p2, p3));
            oacc[nt][0] *= f0; oacc[nt][1] *= f0;
            oacc[nt][2] *= f1; oacc[nt][3] *= f1;
        }
        ps0 += __shfl_xor_sync(0xffffffffu, ps0, 1);
        ps0 += __shfl_xor_sync(0xffffffffu, ps0, 2);
        ps1 += __shfl_xor_sync(0xffffffffu, ps1, 1);
        ps1 += __shfl_xor_sync(0xffffffffu, ps1, 2);
        l0 = l0*f0 + ps0;
        l1 = l1*f1 + ps1;

        // O += P * V : A from registers, B = Vt[d][key]
        #pragma unroll
        for (int s = 0; s < 4; s++) {
            unsigned a[4] = { ph[2*s][0], ph[2*s][1], ph[2*s+1][0], ph[2*s+1][1] };
            unsigned bv[4][4];
            #pragma unroll
            for (int nb = 0; nb < 4; nb++)
                ldsm4(bv[nb], frag_addr(vs, nb*16, s*2, lane));
            #pragma unroll
            for (int nt = 0; nt < 8; nt++) {
                const unsigned* bsrc = bv[nt >> 1];
                unsigned bb[2] = { bsrc[nt & 1], bsrc[(nt & 1) + 2] };
                mma_f16(oacc[nt], a, bb);
            }
        }
        cpa_wait<0>();   // next K/V landed before loop-top sync
    }

    // normalize + write g_att (fp16): d = nt*8 + 2tig
    const float inv0 = 1.0f / l0, inv1 = 1.0f / l1;
    __half* outp = g_att + ((size_t)b*SEQ + (size_t)qt*128)*DMODEL + h*DHEAD;
    #pragma unroll
    for (int nt = 0; nt < 8; nt++) {
        const int d = nt*8 + 2*tig;
        *(__half2*)(outp + (size_t)r_lo*DMODEL + d) =
            __floats2half2_rn(oacc[nt][0]*inv0, oacc[nt][1]*inv0);
        *(__half2*)(outp + (size_t)r_hi*DMODEL + d) =
            __floats2half2_rn(oacc[nt][2]*inv1, oacc[nt][3]*inv1);
    }
}

extern "C" void kernel_launch(void* const* d_in, const int* in_sizes, int n_in,
                              void* d_out, int out_size)
{
    const float* x  = (const float*)d_in[0];
    const float* Qw = (const float*)d_in[1];
    const float* Qb = (const float*)d_in[2];
    const float* Kw = (const float*)d_in[3];
    const float* Kb = (const float*)d_in[4];
    const float* Vw = (const float*)d_in[5];
    const float* Vb = (const float*)d_in[6];
    const float* Ow = (const float*)d_in[7];
    const float* Ob = (const float*)d_in[8];
    float* out = (float*)d_out;

    __half* d_wo; cudaGetSymbolAddress((void**)&d_wo, g_woh);

    // prework: fp16 conversions + weight transposes
    cvt_x_kernel<<<2048, 256>>>(x);
    trw_qkv_kernel<<<dim3(2, 32, 48), dim3(32, 8)>>>(Qw, Kw, Vw);
    trw_kernel<<<dim3(32, 32, 1), dim3(32, 8)>>>(Ow, d_wo, DMODEL, DMODEL);

    cudaFuncSetAttribute(qkv_kernel,
                         cudaFuncAttributeMaxDynamicSharedMemorySize, GEMM_SMEM);
    cudaFuncSetAttribute(oproj_kernel,
                         cudaFuncAttributeMaxDynamicSharedMemorySize, GEMM_SMEM);
    cudaFuncSetAttribute(attn_kernel,
                         cudaFuncAttributeMaxDynamicSharedMemorySize, ATTN_SMEM);

    // QKV projection: 64 m-tiles x 24 (proj x 8 col-tiles)
    qkv_kernel<<<dim3(64, 24), 256, GEMM_SMEM>>>(Qb, Kb, Vb);

    // V transpose for attention B-operand
    trv_kernel<<<dim3(64, 2, BATCH*NH), dim3(32, 8)>>>();

    // Flash attention: 16 q-tiles x 64 (b,h)
    attn_kernel<<<dim3(16, 64), 256, ATTN_SMEM>>>();

    // Output projection: 64 m-tiles x 8 n-tiles
    oproj_kernel<<<dim3(64, 8), 256, GEMM_SMEM>>>(Ob, out);
}